// round 1
// baseline (speedup 1.0000x reference)
#include <cuda_runtime.h>
#include <cstdint>

// Problem constants (fixed shapes from reference)
#define NUM_CLASSES 16
#define C_IN 21
#define D_HID 12      // 2*NUM_PARTS
#define P_OUT 7       // NUM_PARTS+1
#define BS 4
#define V 8
#define N_IMG (BS*V)  // 32
#define H 128
#define W 128
#define HW (H*W)      // 16384
#define EPS 1e-5f

#define PIX_PER_THREAD 2
#define THREADS 256
#define PIX_PER_BLOCK (THREADS * PIX_PER_THREAD)        // 512
#define BLOCKS_PER_IMG (HW / PIX_PER_BLOCK)             // 32
#define GRID (N_IMG * BLOCKS_PER_IMG)                   // 1024

// Output layout: tuple (out, feats) flattened:
//   out:   (32, 7, 128, 128)  -> 3,670,016 floats at offset 0
//   feats: (32, 21, 128, 128) -> 11,010,048 floats after it
#define OUT_ELEMS ((size_t)N_IMG * P_OUT * HW)

__global__ __launch_bounds__(THREADS)
void mvpartseg_fused_kernel(const float* __restrict__ x,     // (32,21,128,128)
                            const int*   __restrict__ cls,   // (4,1)
                            const float* __restrict__ W1,    // (16,12,21)
                            const float* __restrict__ b1,    // (16,12)
                            const float* __restrict__ g1,    // (16,12)
                            const float* __restrict__ be1,   // (16,12)
                            const float* __restrict__ rm1,   // (16,12)
                            const float* __restrict__ rv1,   // (16,12)
                            const float* __restrict__ W2,    // (16,7,12)
                            const float* __restrict__ b2,    // (16,7)
                            float* __restrict__ out)
{
    __shared__ float sA1[D_HID * C_IN];  // BN-folded layer-1 weights (252)
    __shared__ float sc1[D_HID];         // BN-folded layer-1 bias
    __shared__ float sA2[P_OUT * D_HID]; // layer-2 weights (84)
    __shared__ float sb2[P_OUT];
    __shared__ float sinv[D_HID];

    const int t = threadIdx.x;
    const int n = blockIdx.x / BLOCKS_PER_IMG;       // image (view-folded) index
    const int k = cls[n / V];                        // selected class head

    // Fold BN into conv1 params
    if (t < D_HID) {
        const int i = k * D_HID + t;
        float inv = g1[i] * rsqrtf(rv1[i] + EPS);
        sinv[t] = inv;
        sc1[t]  = b1[i] * inv + be1[i] - rm1[i] * inv;
    }
    if (t < P_OUT) sb2[t] = b2[k * P_OUT + t];
    __syncthreads();

    for (int i = t; i < D_HID * C_IN; i += THREADS) {
        int d = i / C_IN;
        sA1[i] = W1[k * D_HID * C_IN + i] * sinv[d];
    }
    for (int i = t; i < P_OUT * D_HID; i += THREADS) {
        sA2[i] = W2[k * P_OUT * D_HID + i];
    }
    __syncthreads();

    const int pix = (blockIdx.x % BLOCKS_PER_IMG) * PIX_PER_BLOCK + t * PIX_PER_THREAD;
    const size_t in_base = (size_t)n * C_IN * HW;

    // Load 21 channels for 2 adjacent pixels (float2, coalesced)
    float2 xv[C_IN];
#pragma unroll
    for (int c = 0; c < C_IN; c++) {
        xv[c] = *(const float2*)(x + in_base + (size_t)c * HW + pix);
    }

    // feats output = identity copy of input (same memory layout)
    float* feats = out + OUT_ELEMS;
#pragma unroll
    for (int c = 0; c < C_IN; c++) {
        *(float2*)(feats + in_base + (size_t)c * HW + pix) = xv[c];
    }

    // Per-pixel MLP: relu(A1 x + c1) -> relu(A2 h + b2)
    float res[P_OUT][PIX_PER_THREAD];
#pragma unroll
    for (int s = 0; s < PIX_PER_THREAD; s++) {
        float h1[D_HID];
#pragma unroll
        for (int d = 0; d < D_HID; d++) {
            float acc = sc1[d];
#pragma unroll
            for (int c = 0; c < C_IN; c++) {
                float xs = (s == 0) ? xv[c].x : xv[c].y;
                acc = fmaf(sA1[d * C_IN + c], xs, acc);
            }
            h1[d] = fmaxf(acc, 0.0f);
        }
#pragma unroll
        for (int p = 0; p < P_OUT; p++) {
            float acc = sb2[p];
#pragma unroll
            for (int d = 0; d < D_HID; d++) {
                acc = fmaf(sA2[p * D_HID + d], h1[d], acc);
            }
            // max over masked classes includes zeros from the 15 unselected
            // heads -> relu of the selected head's logits
            res[p][s] = fmaxf(acc, 0.0f);
        }
    }

    const size_t out_base = (size_t)n * P_OUT * HW + pix;
#pragma unroll
    for (int p = 0; p < P_OUT; p++) {
        *(float2*)(out + out_base + (size_t)p * HW) = make_float2(res[p][0], res[p][1]);
    }
}

extern "C" void kernel_launch(void* const* d_in, const int* in_sizes, int n_in,
                              void* d_out, int out_size)
{
    const float* x   = (const float*)d_in[0];
    const int*   cls = (const int*)  d_in[1];
    const float* W1  = (const float*)d_in[2];
    const float* b1  = (const float*)d_in[3];
    const float* g1  = (const float*)d_in[4];
    const float* be1 = (const float*)d_in[5];
    const float* rm1 = (const float*)d_in[6];
    const float* rv1 = (const float*)d_in[7];
    const float* W2  = (const float*)d_in[8];
    const float* b2  = (const float*)d_in[9];
    float* out = (float*)d_out;

    mvpartseg_fused_kernel<<<GRID, THREADS>>>(x, cls, W1, b1, g1, be1, rm1, rv1,
                                              W2, b2, out);
}

// round 2
// speedup vs baseline: 1.3563x; 1.3563x over previous
#include <cuda_runtime.h>
#include <cstdint>

// Problem constants (fixed shapes from reference)
#define NUM_CLASSES 16
#define C_IN 21
#define D_HID 12      // 2*NUM_PARTS
#define P_OUT 7       // NUM_PARTS+1
#define BS 4
#define V 8
#define N_IMG (BS*V)  // 32
#define H 128
#define W 128
#define HW (H*W)      // 16384
#define EPS 1e-5f

#define PIX_PER_THREAD 4
#define THREADS 256
#define PIX_PER_BLOCK (THREADS * PIX_PER_THREAD)        // 1024
#define BLOCKS_PER_IMG (HW / PIX_PER_BLOCK)             // 16
#define GRID (N_IMG * BLOCKS_PER_IMG)                   // 512

// Output layout: tuple (out, feats) flattened:
//   out:   (32, 7, 128, 128)  -> 3,670,016 floats at offset 0
//   feats: (32, 21, 128, 128) -> 11,010,048 floats after it
#define OUT_ELEMS ((size_t)N_IMG * P_OUT * HW)

__global__ __launch_bounds__(THREADS, 3)
void mvpartseg_fused_kernel(const float* __restrict__ x,     // (32,21,128,128)
                            const int*   __restrict__ cls,   // (4,1)
                            const float* __restrict__ W1,    // (16,12,21)
                            const float* __restrict__ b1,    // (16,12)
                            const float* __restrict__ g1,    // (16,12)
                            const float* __restrict__ be1,   // (16,12)
                            const float* __restrict__ rm1,   // (16,12)
                            const float* __restrict__ rv1,   // (16,12)
                            const float* __restrict__ W2,    // (16,7,12)
                            const float* __restrict__ b2,    // (16,7)
                            float* __restrict__ out)
{
    // Layer-1 weights transposed to [c][d] so the 12 per-channel weights are
    // contiguous -> LDS.128 x3 per channel instead of 12 scalar LDS.
    __shared__ float sA1t[C_IN * D_HID];   // 252, BN-folded
    __shared__ float sc1[D_HID];           // BN-folded layer-1 bias
    __shared__ float sA2[P_OUT * D_HID];   // 84, [p][d] (contiguous per p)
    __shared__ float sb2[P_OUT];
    __shared__ float sinv[D_HID];

    const int t = threadIdx.x;
    const int n = blockIdx.x / BLOCKS_PER_IMG;       // image (view-folded) index
    const int k = cls[n / V];                        // selected class head

    // Fold BN into conv1 params
    if (t < D_HID) {
        const int i = k * D_HID + t;
        float inv = g1[i] * rsqrtf(rv1[i] + EPS);
        sinv[t] = inv;
        sc1[t]  = b1[i] * inv + be1[i] - rm1[i] * inv;
    }
    if (t < P_OUT) sb2[t] = b2[k * P_OUT + t];
    __syncthreads();

    for (int i = t; i < C_IN * D_HID; i += THREADS) {
        int c = i / D_HID, d = i % D_HID;
        sA1t[i] = W1[k * D_HID * C_IN + d * C_IN + c] * sinv[d];
    }
    for (int i = t; i < P_OUT * D_HID; i += THREADS) {
        sA2[i] = W2[k * P_OUT * D_HID + i];
    }
    __syncthreads();

    const int pix = (blockIdx.x % BLOCKS_PER_IMG) * PIX_PER_BLOCK + t * PIX_PER_THREAD;
    const size_t in_base = (size_t)n * C_IN * HW;
    float* feats = out + OUT_ELEMS;

    // Layer-1 accumulators for 4 pixels, initialized to folded bias
    float4 acc[D_HID];
#pragma unroll
    for (int d = 0; d < D_HID; d++) {
        float c1 = sc1[d];
        acc[d] = make_float4(c1, c1, c1, c1);
    }

    // Stream channels: load (float4), copy to feats (streaming store),
    // FMA into the 12 hidden accumulators.
#pragma unroll
    for (int c = 0; c < C_IN; c++) {
        const float4 xv = *(const float4*)(x + in_base + (size_t)c * HW + pix);
        __stcs((float4*)(feats + in_base + (size_t)c * HW + pix), xv);
#pragma unroll
        for (int d = 0; d < D_HID; d++) {
            const float w = sA1t[c * D_HID + d];
            acc[d].x = fmaf(w, xv.x, acc[d].x);
            acc[d].y = fmaf(w, xv.y, acc[d].y);
            acc[d].z = fmaf(w, xv.z, acc[d].z);
            acc[d].w = fmaf(w, xv.w, acc[d].w);
        }
    }

    // ReLU hidden
#pragma unroll
    for (int d = 0; d < D_HID; d++) {
        acc[d].x = fmaxf(acc[d].x, 0.0f);
        acc[d].y = fmaxf(acc[d].y, 0.0f);
        acc[d].z = fmaxf(acc[d].z, 0.0f);
        acc[d].w = fmaxf(acc[d].w, 0.0f);
    }

    // Layer 2 + final relu (max over masked classes == relu of selected head)
    const size_t out_base = (size_t)n * P_OUT * HW + pix;
#pragma unroll
    for (int p = 0; p < P_OUT; p++) {
        float bb = sb2[p];
        float4 o = make_float4(bb, bb, bb, bb);
#pragma unroll
        for (int d = 0; d < D_HID; d++) {
            const float w = sA2[p * D_HID + d];
            o.x = fmaf(w, acc[d].x, o.x);
            o.y = fmaf(w, acc[d].y, o.y);
            o.z = fmaf(w, acc[d].z, o.z);
            o.w = fmaf(w, acc[d].w, o.w);
        }
        o.x = fmaxf(o.x, 0.0f);
        o.y = fmaxf(o.y, 0.0f);
        o.z = fmaxf(o.z, 0.0f);
        o.w = fmaxf(o.w, 0.0f);
        __stcs((float4*)(out + out_base + (size_t)p * HW), o);
    }
}

extern "C" void kernel_launch(void* const* d_in, const int* in_sizes, int n_in,
                              void* d_out, int out_size)
{
    const float* x   = (const float*)d_in[0];
    const int*   cls = (const int*)  d_in[1];
    const float* W1  = (const float*)d_in[2];
    const float* b1  = (const float*)d_in[3];
    const float* g1  = (const float*)d_in[4];
    const float* be1 = (const float*)d_in[5];
    const float* rm1 = (const float*)d_in[6];
    const float* rv1 = (const float*)d_in[7];
    const float* W2  = (const float*)d_in[8];
    const float* b2  = (const float*)d_in[9];
    float* out = (float*)d_out;

    mvpartseg_fused_kernel<<<GRID, THREADS>>>(x, cls, W1, b1, g1, be1, rm1, rv1,
                                              W2, b2, out);
}